// round 8
// baseline (speedup 1.0000x reference)
#include <cuda_runtime.h>
#include <cuda_fp16.h>
#include <cstdint>
#include <math.h>

// ---------------------------------------------------------------------------
// Problem constants
// ---------------------------------------------------------------------------
#define B_     4096
#define NIN    2048
#define NOUT   2048
#define KTOT   4096              // NIN + NOUT
#define NTOT   8192              // 4 * NOUT

// GEMM tiling: 128(M) x 128(N-packed) x 64(K), 256 threads, 8 warps (4m x 2n),
// warp tile 32x64, 2 CTAs/SM. A via fragment-LDG from L2, B via smem.
#define BM     128
#define BN     128
#define BK     64
#define STG    3
#define B_STAGE_B  (BN * BK * 2)             // 16384 (B tile only)
#define EPI_PITCH  132                        // fp32 words per row (128 + 4 pad)
#define SMEM_TOTAL 67584                      // max(3*16384, 128*132*4)

// ---------------------------------------------------------------------------
// Device scratch (static; no allocation allowed)
// ---------------------------------------------------------------------------
// A in mma-fragment layout: block (m16, k16) -> 32 lanes x uint4 (a0..a3).
// idx(uint4) = ((m16*256 + k16)*32 + lane);  256 m16-blocks x 256 k16-blocks.
__device__ __align__(16) uint4  g_Tfrag[(size_t)256 * 256 * 32];   // 32 MB
__device__ __align__(16) __half g_Wh[(size_t)NTOT * KTOT];         // 64 MB (rows: j*4+gate)

// ---------------------------------------------------------------------------
// Helpers
// ---------------------------------------------------------------------------
__device__ __forceinline__ uint32_t smem_u32(const void* p) {
    uint32_t a;
    asm("{ .reg .u64 t; cvta.to.shared.u64 t, %1; cvt.u32.u64 %0, t; }" : "=r"(a) : "l"(p));
    return a;
}

__device__ __forceinline__ uint32_t swz(uint32_t off) {
    return off ^ ((off >> 3) & 0x70);     // 128B-row swizzle
}

__device__ __forceinline__ void cp16(uint32_t dst, const void* src) {
    asm volatile("cp.async.cg.shared.global [%0], [%1], 16;" :: "r"(dst), "l"(src));
}

__device__ __forceinline__ void ldsm4(uint32_t* d, uint32_t addr) {
    asm volatile("ldmatrix.sync.aligned.m8n8.x4.shared.b16 {%0,%1,%2,%3}, [%4];"
                 : "=r"(d[0]), "=r"(d[1]), "=r"(d[2]), "=r"(d[3]) : "r"(addr));
}

__device__ __forceinline__ void mma16816(float* c,
                                         uint32_t a0, uint32_t a1, uint32_t a2, uint32_t a3,
                                         uint32_t b0, uint32_t b1) {
    asm volatile("mma.sync.aligned.m16n8k16.row.col.f32.f16.f16.f32 "
                 "{%0,%1,%2,%3}, {%4,%5,%6,%7}, {%8,%9}, {%0,%1,%2,%3};"
                 : "+f"(c[0]), "+f"(c[1]), "+f"(c[2]), "+f"(c[3])
                 : "r"(a0), "r"(a1), "r"(a2), "r"(a3), "r"(b0), "r"(b1));
}

__device__ __forceinline__ float sigmoidf_(float z) { return 1.0f / (1.0f + expf(-z)); }

__device__ __forceinline__ uint32_t packh2(float a, float b) {
    __half2 p = __floats2half2_rn(a, b);
    return *reinterpret_cast<uint32_t*>(&p);
}

// ---------------------------------------------------------------------------
// conv_T_frag: T = concat(x, h) -> A fragments (coalesced uint4 stores).
// One thread per (m16, k16, lane). Fragment mapping for mma.m16n8k16 A:
//   a0 = T[m16*16 + l/4    ][k16*16 + (l%4)*2 .. +1]
//   a1 = T[m16*16 + l/4 + 8][same k]
//   a2 = T[m16*16 + l/4    ][k16*16 + 8 + (l%4)*2 .. +1]
//   a3 = T[m16*16 + l/4 + 8][same k]
// ---------------------------------------------------------------------------
__global__ void __launch_bounds__(256)
conv_T_frag_kernel(const float* __restrict__ x, const float* __restrict__ h) {
    uint32_t g = blockIdx.x * 256 + threadIdx.x;     // 256*256*32 = 2M threads
    uint32_t lane = g & 31;
    uint32_t blk  = g >> 5;          // m16*256 + k16
    uint32_t k16  = blk & 255;
    uint32_t m16  = blk >> 8;

    uint32_t row0 = m16 * 16 + (lane >> 2);
    uint32_t col  = k16 * 16 + (lane & 3) * 2;       // 16-aligned block, pairs stay inside

    // element (r, c) of T: c < NIN -> x[r][c], else h[r][c-NIN]
    auto ld2 = [&](uint32_t r, uint32_t c) -> float2 {
        const float* src = (c < NIN) ? (x + (size_t)r * NIN + c)
                                     : (h + (size_t)r * NOUT + (c - NIN));
        return *reinterpret_cast<const float2*>(src);
    };

    float2 r0a = ld2(row0,     col);
    float2 r1a = ld2(row0 + 8, col);
    float2 r0b = ld2(row0,     col + 8);
    float2 r1b = ld2(row0 + 8, col + 8);

    uint4 v;
    v.x = packh2(r0a.x, r0a.y);
    v.y = packh2(r1a.x, r1a.y);
    v.z = packh2(r0b.x, r0b.y);
    v.w = packh2(r1b.x, r1b.y);
    g_Tfrag[(size_t)blk * 32 + lane] = v;
}

// ---------------------------------------------------------------------------
// conv_W: packed rows p = j*4 + gate, K-major fp16 (staged into smem by GEMM).
// ---------------------------------------------------------------------------
__device__ __forceinline__ uint4 pack8_h(const float* src) {
    float4 v0 = *reinterpret_cast<const float4*>(src);
    float4 v1 = *reinterpret_cast<const float4*>(src + 4);
    uint4 o;
    o.x = packh2(v0.x, v0.y);
    o.y = packh2(v0.z, v0.w);
    o.z = packh2(v1.x, v1.y);
    o.w = packh2(v1.z, v1.w);
    return o;
}

__global__ void __launch_bounds__(256)
conv_W_kernel(const float* __restrict__ Wf, const float* __restrict__ Wi,
              const float* __restrict__ Wo, const float* __restrict__ Wg) {
    uint32_t idx = blockIdx.x * 256 + threadIdx.x;   // NTOT * 512 threads
    uint32_t jall = idx >> 9;                         // 0..8191 (gate*2048 + j)
    uint32_t k = (idx & 511) * 8;
    uint32_t gate = jall >> 11;
    uint32_t j = jall & 2047;
    const float* W = (gate == 0) ? Wf : (gate == 1) ? Wi : (gate == 2) ? Wo : Wg;
    uint32_t p = j * 4 + gate;
    *reinterpret_cast<uint4*>(g_Wh + (size_t)p * KTOT + k) =
        pack8_h(W + (size_t)j * KTOT + k);
}

// ---------------------------------------------------------------------------
// Fused GEMM + LSTM epilogue. B staged via cp.async (3 stages x 16KB);
// A fragments LDG'd from L2-resident g_Tfrag with 1-kstep prefetch.
// grid = 2048 (mt = bid&31, nt = bid>>5), 256 threads.
// ---------------------------------------------------------------------------
__device__ __forceinline__ void stage_B(uint32_t sB, const __half* __restrict__ gB,
                                        int k0, int t) {
    // 128 rows x 8 chunks of 16B = 1024 chunks -> 4 per thread
#pragma unroll
    for (int i = 0; i < 4; i++) {
        int c = t + i * 256;
        int row = c >> 3, c16 = c & 7;
        uint32_t off = row * 128 + c16 * 16;
        cp16(sB + swz(off), gB + (size_t)row * KTOT + k0 + c16 * 8);
    }
}

__global__ void __launch_bounds__(256, 2)
lstm_gemm_fused_kernel(const float* __restrict__ c_old,
                       const float* __restrict__ bf,
                       const float* __restrict__ bi,
                       const float* __restrict__ bo,
                       const float* __restrict__ bg,
                       float* __restrict__ out) {
    extern __shared__ __align__(1024) char smem[];
    const uint32_t sbase = smem_u32(smem);

    const int t    = threadIdx.x;
    const int lane = t & 31;
    const int wid  = t >> 5;      // 0..7
    const int wm   = wid & 3;     // warp m band: 32 rows (2 m16 blocks)
    const int wn   = wid >> 2;    // warp n band: 64 packed cols

    const int bid = blockIdx.x;
    const int mt = bid & 31;
    const int nt = bid >> 5;
    const int m0 = mt * BM;
    const int p0 = nt * BN;       // packed col base
    const int j0 = nt * 32;       // j base

    const __half* gB = g_Wh + (size_t)p0 * KTOT;
    // A fragment base for this warp: m16 index = mt*8 + wm*2 (+mf), uint4 units
    const uint4* __restrict__ aF =
        g_Tfrag + ((size_t)(mt * 8 + wm * 2) * 256) * 32 + lane;

    float acc[2][8][4];           // [mf][n8][quad]
#pragma unroll
    for (int i = 0; i < 2; i++)
#pragma unroll
        for (int j = 0; j < 8; j++)
#pragma unroll
            for (int q = 0; q < 4; q++) acc[i][j][q] = 0.0f;

    stage_B(sbase, gB, 0, t);
    asm volatile("cp.async.commit_group;" ::: "memory");
    stage_B(sbase + B_STAGE_B, gB, BK, t);
    asm volatile("cp.async.commit_group;" ::: "memory");

    const int lrow = lane & 15;
    const int lkof = (lane & 16) ? 8 : 0;

    // prefetch A fragments for k16 = 0
    uint4 a_cur[2], a_nxt[2];
    a_cur[0] = aF[0];
    a_cur[1] = aF[256 * 32];

    const int NIT = KTOT / BK;     // 64
    for (int it = 0; it < NIT; it++) {
        asm volatile("cp.async.wait_group 1;" ::: "memory");
        __syncthreads();

        if (it + 2 < NIT) {
            int sn = (it + 2) % STG;
            stage_B(sbase + sn * B_STAGE_B, gB, (it + 2) * BK, t);
            asm volatile("cp.async.commit_group;" ::: "memory");
        }

        const uint32_t aB = sbase + (it % STG) * B_STAGE_B;

#pragma unroll
        for (int kk = 0; kk < 4; kk++) {
            // prefetch A fragments for next k16 step
            int k16n = it * 4 + kk + 1;
            if (k16n < 256) {
                a_nxt[0] = aF[(size_t)k16n * 32];
                a_nxt[1] = aF[(size_t)(256 + k16n) * 32];
            }

            uint32_t b[4][4];
#pragma unroll
            for (int nf = 0; nf < 4; nf++) {
                uint32_t off = (uint32_t)(wn * 64 + nf * 16 + lrow) * 128
                             + (uint32_t)(kk * 16 + lkof) * 2;
                ldsm4(b[nf], aB + swz(off));
            }
#pragma unroll
            for (int nf = 0; nf < 4; nf++) {
                mma16816(acc[0][nf * 2],     a_cur[0].x, a_cur[0].y, a_cur[0].z, a_cur[0].w,
                         b[nf][0], b[nf][2]);
                mma16816(acc[0][nf * 2 + 1], a_cur[0].x, a_cur[0].y, a_cur[0].z, a_cur[0].w,
                         b[nf][1], b[nf][3]);
                mma16816(acc[1][nf * 2],     a_cur[1].x, a_cur[1].y, a_cur[1].z, a_cur[1].w,
                         b[nf][0], b[nf][2]);
                mma16816(acc[1][nf * 2 + 1], a_cur[1].x, a_cur[1].y, a_cur[1].z, a_cur[1].w,
                         b[nf][1], b[nf][3]);
            }
            a_cur[0] = a_nxt[0];
            a_cur[1] = a_nxt[1];
        }
    }

    // ---- drain pipeline, then reuse smem as fp32 Z tile [128][EPI_PITCH] ----
    asm volatile("cp.async.wait_group 0;" ::: "memory");
    __syncthreads();

    float* zt = reinterpret_cast<float*>(smem);
    {
        const int r0 = wm * 32 + (lane >> 2);
        const int c0 = wn * 64 + (lane & 3) * 2;
#pragma unroll
        for (int mf = 0; mf < 2; mf++) {
            int row = r0 + mf * 16;
#pragma unroll
            for (int n8 = 0; n8 < 8; n8++) {
                int pc = c0 + n8 * 8;
                *reinterpret_cast<float2*>(&zt[(size_t)row * EPI_PITCH + pc]) =
                    make_float2(acc[mf][n8][0], acc[mf][n8][1]);
                *reinterpret_cast<float2*>(&zt[(size_t)(row + 8) * EPI_PITCH + pc]) =
                    make_float2(acc[mf][n8][2], acc[mf][n8][3]);
            }
        }
    }
    __syncthreads();

    // ---- fused LSTM epilogue: warp -> 16-row block, lane -> j ----
    {
        const int j = lane;                  // 0..31
        const int jg = j0 + j;
        const float bfs = bf[jg];
        const float bis = bi[jg];
        const float bos = bo[jg];
        const float bgs = bg[jg];
#pragma unroll
        for (int i = 0; i < 16; i++) {
            int ml = wid * 16 + i;
            float4 z = *reinterpret_cast<const float4*>(&zt[(size_t)ml * EPI_PITCH + j * 4]);
            float zf = z.x + bfs;
            float zi = z.y + bis;
            float zo = z.z + bos;
            float zg = z.w + bgs;
            int m = m0 + ml;
            float co = c_old[(size_t)m * NOUT + jg];
            float f  = sigmoidf_(zf);
            float ii = sigmoidf_(zi);
            float oo = sigmoidf_(zo);
            float g  = tanhf(zg);
            float c  = f * co + ii * g;
            float hh = oo * tanhf(c);
            out[(size_t)m * NOUT + jg] = c;
            out[(size_t)B_ * NOUT + (size_t)m * NOUT + jg] = hh;
        }
    }
}

// ---------------------------------------------------------------------------
// kernel_launch
// Input order: c_old, h_old, x, Wf, bf, Wi, bi, Wo, bo, Wg, bg, mode
// ---------------------------------------------------------------------------
extern "C" void kernel_launch(void* const* d_in, const int* in_sizes, int n_in,
                              void* d_out, int out_size) {
    const float* c_old = (const float*)d_in[0];
    const float* h_old = (const float*)d_in[1];
    const float* x     = (const float*)d_in[2];
    const float* Wf    = (const float*)d_in[3];
    const float* bf    = (const float*)d_in[4];
    const float* Wi    = (const float*)d_in[5];
    const float* bi    = (const float*)d_in[6];
    const float* Wo    = (const float*)d_in[7];
    const float* bo    = (const float*)d_in[8];
    const float* Wg    = (const float*)d_in[9];
    const float* bg    = (const float*)d_in[10];
    float* out = (float*)d_out;

    static int configured = 0;
    if (!configured) {
        cudaFuncSetAttribute(lstm_gemm_fused_kernel,
                             cudaFuncAttributeMaxDynamicSharedMemorySize, SMEM_TOTAL);
        configured = 1;
    }

    conv_T_frag_kernel<<<(256 * 256 * 32) / 256, 256>>>(x, h_old);
    conv_W_kernel<<<(NTOT * 512) / 256, 256>>>(Wf, Wi, Wo, Wg);

    lstm_gemm_fused_kernel<<<(B_ / BM) * (NTOT / BN), 256, SMEM_TOTAL>>>(
        c_old, bf, bi, bo, bg, out);
}

// round 9
// speedup vs baseline: 1.0430x; 1.0430x over previous
#include <cuda_runtime.h>
#include <cuda_fp16.h>
#include <cstdint>
#include <math.h>

// ---------------------------------------------------------------------------
// Problem constants
// ---------------------------------------------------------------------------
#define B_     4096
#define NIN    2048
#define NOUT   2048
#define KTOT   4096              // NIN + NOUT
#define NTOT   8192              // 4 * NOUT

// GEMM tiling: 128(M) x 128(N-packed) x 64(K), 256 threads, 8 warps (4m x 2n),
// warp tile 32x64, 2 CTAs/SM, register double-buffered fragments.
#define BM     128
#define BN     128
#define BK     64
#define STG    3
#define A_STAGE_B  (BM * BK * 2)             // 16384
#define B_STAGE_B  (BN * BK * 2)             // 16384
#define STAGE_B    (A_STAGE_B + B_STAGE_B)   // 32768
#define SMEM_TOTAL (STG * STAGE_B)           // 98304 -> 2 CTAs/SM
#define EPI_PITCH  132                        // fp32 words per row (128 + 4 pad)

// ---------------------------------------------------------------------------
// Device scratch (static; no allocation allowed)
// ---------------------------------------------------------------------------
__device__ __align__(16) __half g_Th[(size_t)B_ * KTOT];     // 32 MB
__device__ __align__(16) __half g_Wh[(size_t)NTOT * KTOT];   // 64 MB (rows: j*4+gate)

// ---------------------------------------------------------------------------
// Helpers
// ---------------------------------------------------------------------------
__device__ __forceinline__ uint32_t smem_u32(const void* p) {
    uint32_t a;
    asm("{ .reg .u64 t; cvta.to.shared.u64 t, %1; cvt.u32.u64 %0, t; }" : "=r"(a) : "l"(p));
    return a;
}

__device__ __forceinline__ uint32_t swz(uint32_t off) {
    return off ^ ((off >> 3) & 0x70);     // 128B-row swizzle
}

__device__ __forceinline__ void cp16(uint32_t dst, const void* src) {
    asm volatile("cp.async.cg.shared.global [%0], [%1], 16;" :: "r"(dst), "l"(src));
}

__device__ __forceinline__ void ldsm4(uint32_t* d, uint32_t addr) {
    asm volatile("ldmatrix.sync.aligned.m8n8.x4.shared.b16 {%0,%1,%2,%3}, [%4];"
                 : "=r"(d[0]), "=r"(d[1]), "=r"(d[2]), "=r"(d[3]) : "r"(addr));
}

__device__ __forceinline__ void mma16816(float* c,
                                         uint32_t a0, uint32_t a1, uint32_t a2, uint32_t a3,
                                         uint32_t b0, uint32_t b1) {
    asm volatile("mma.sync.aligned.m16n8k16.row.col.f32.f16.f16.f32 "
                 "{%0,%1,%2,%3}, {%4,%5,%6,%7}, {%8,%9}, {%0,%1,%2,%3};"
                 : "+f"(c[0]), "+f"(c[1]), "+f"(c[2]), "+f"(c[3])
                 : "r"(a0), "r"(a1), "r"(a2), "r"(a3), "r"(b0), "r"(b1));
}

__device__ __forceinline__ float sigmoidf_(float z) { return 1.0f / (1.0f + expf(-z)); }

__device__ __forceinline__ uint32_t packh2(float a, float b) {
    __half2 p = __floats2half2_rn(a, b);
    return *reinterpret_cast<uint32_t*>(&p);
}

// ---------------------------------------------------------------------------
// Fused conversion kernel: fp32 -> fp16 for both T and packed W.
// Blocks [0, 8192): T rows.  Blocks [8192, 24576): W rows (p = j*4 + gate).
// ---------------------------------------------------------------------------
__device__ __forceinline__ uint4 pack8_h(const float* src) {
    float4 v0 = *reinterpret_cast<const float4*>(src);
    float4 v1 = *reinterpret_cast<const float4*>(src + 4);
    uint4 o;
    o.x = packh2(v0.x, v0.y);
    o.y = packh2(v0.z, v0.w);
    o.z = packh2(v1.x, v1.y);
    o.w = packh2(v1.z, v1.w);
    return o;
}

#define T_BLOCKS ((B_ * 512) / 256)          // 8192
#define W_BLOCKS ((NTOT * 512) / 256)        // 16384

__global__ void __launch_bounds__(256)
conv_all_kernel(const float* __restrict__ x, const float* __restrict__ h,
                const float* __restrict__ Wf, const float* __restrict__ Wi,
                const float* __restrict__ Wo, const float* __restrict__ Wg) {
    uint32_t b = blockIdx.x;
    if (b < T_BLOCKS) {
        uint32_t idx = b * 256 + threadIdx.x;
        uint32_t m = idx >> 9;
        uint32_t k = (idx & 511) * 8;
        const float* src = (k < NIN) ? (x + (size_t)m * NIN + k)
                                     : (h + (size_t)m * NOUT + (k - NIN));
        *reinterpret_cast<uint4*>(g_Th + (size_t)m * KTOT + k) = pack8_h(src);
    } else {
        uint32_t idx = (b - T_BLOCKS) * 256 + threadIdx.x;
        uint32_t jall = idx >> 9;                 // gate*2048 + j
        uint32_t k = (idx & 511) * 8;
        uint32_t gate = jall >> 11;
        uint32_t j = jall & 2047;
        const float* W = (gate == 0) ? Wf : (gate == 1) ? Wi : (gate == 2) ? Wo : Wg;
        uint32_t p = j * 4 + gate;
        *reinterpret_cast<uint4*>(g_Wh + (size_t)p * KTOT + k) =
            pack8_h(W + (size_t)j * KTOT + k);
    }
}

// ---------------------------------------------------------------------------
// Fused GEMM + LSTM epilogue with register double-buffered fragments.
// grid = 2048 (mt = bid&31, nt = bid>>5), 256 threads, 3-stage cp.async.
// ---------------------------------------------------------------------------
__device__ __forceinline__ void stage_slab(uint32_t sA, uint32_t sB,
                                           const __half* __restrict__ gA,
                                           const __half* __restrict__ gB,
                                           int k0, int t) {
#pragma unroll
    for (int i = 0; i < 4; i++) {
        int c = t + i * 256;
        int row = c >> 3, c16 = c & 7;
        uint32_t off = row * 128 + c16 * 16;
        cp16(sA + swz(off), gA + (size_t)row * KTOT + k0 + c16 * 8);
    }
#pragma unroll
    for (int i = 0; i < 4; i++) {
        int c = t + i * 256;
        int row = c >> 3, c16 = c & 7;
        uint32_t off = row * 128 + c16 * 16;
        cp16(sB + swz(off), gB + (size_t)row * KTOT + k0 + c16 * 8);
    }
}

__device__ __forceinline__ void load_frags(uint32_t a[2][4], uint32_t b[4][4],
                                           uint32_t aA, uint32_t aB, int kk,
                                           int wm, int wn, int lrow, int lkof) {
    uint32_t kcol = (uint32_t)(kk * 16 + lkof) * 2;
#pragma unroll
    for (int mf = 0; mf < 2; mf++) {
        uint32_t off = (uint32_t)(wm * 32 + mf * 16 + lrow) * 128 + kcol;
        ldsm4(a[mf], aA + swz(off));
    }
#pragma unroll
    for (int nf = 0; nf < 4; nf++) {
        uint32_t off = (uint32_t)(wn * 64 + nf * 16 + lrow) * 128 + kcol;
        ldsm4(b[nf], aB + swz(off));
    }
}

__device__ __forceinline__ void mma_block(float acc[2][8][4],
                                          uint32_t a[2][4], uint32_t b[4][4]) {
#pragma unroll
    for (int nf = 0; nf < 4; nf++) {
#pragma unroll
        for (int mf = 0; mf < 2; mf++) {
            mma16816(acc[mf][nf * 2],     a[mf][0], a[mf][1], a[mf][2], a[mf][3],
                     b[nf][0], b[nf][2]);
            mma16816(acc[mf][nf * 2 + 1], a[mf][0], a[mf][1], a[mf][2], a[mf][3],
                     b[nf][1], b[nf][3]);
        }
    }
}

__global__ void __launch_bounds__(256, 2)
lstm_gemm_fused_kernel(const float* __restrict__ c_old,
                       const float* __restrict__ bf,
                       const float* __restrict__ bi,
                       const float* __restrict__ bo,
                       const float* __restrict__ bg,
                       float* __restrict__ out) {
    extern __shared__ __align__(1024) char smem[];
    const uint32_t sbase = smem_u32(smem);

    const int t    = threadIdx.x;
    const int lane = t & 31;
    const int wid  = t >> 5;      // 0..7
    const int wm   = wid & 3;     // warp m band: 32 rows
    const int wn   = wid >> 2;    // warp n band: 64 packed cols

    const int bid = blockIdx.x;
    const int mt = bid & 31;
    const int nt = bid >> 5;
    const int m0 = mt * BM;
    const int p0 = nt * BN;       // packed col base
    const int j0 = nt * 32;       // j base

    const __half* gA = g_Th + (size_t)m0 * KTOT;
    const __half* gB = g_Wh + (size_t)p0 * KTOT;

    float acc[2][8][4];           // [mf][n8][quad]
#pragma unroll
    for (int i = 0; i < 2; i++)
#pragma unroll
        for (int j = 0; j < 8; j++)
#pragma unroll
            for (int q = 0; q < 4; q++) acc[i][j][q] = 0.0f;

    stage_slab(sbase, sbase + A_STAGE_B, gA, gB, 0, t);
    asm volatile("cp.async.commit_group;" ::: "memory");
    stage_slab(sbase + STAGE_B, sbase + STAGE_B + A_STAGE_B, gA, gB, BK, t);
    asm volatile("cp.async.commit_group;" ::: "memory");

    const int lrow = lane & 15;
    const int lkof = (lane & 16) ? 8 : 0;

    uint32_t afr[2][2][4];        // [buf][mf][reg]
    uint32_t bfr[2][4][4];        // [buf][nf][reg]

    const int NIT = KTOT / BK;     // 64
    for (int it = 0; it < NIT; it++) {
        asm volatile("cp.async.wait_group 1;" ::: "memory");
        __syncthreads();

        if (it + 2 < NIT) {
            int sn = (it + 2) % STG;
            stage_slab(sbase + sn * STAGE_B, sbase + sn * STAGE_B + A_STAGE_B,
                       gA, gB, (it + 2) * BK, t);
            asm volatile("cp.async.commit_group;" ::: "memory");
        }

        const int s = it % STG;
        const uint32_t aA = sbase + s * STAGE_B;
        const uint32_t aB = aA + A_STAGE_B;

        // prime kk = 0 fragments
        load_frags(afr[0], bfr[0], aA, aB, 0, wm, wn, lrow, lkof);

#pragma unroll
        for (int kk = 0; kk < 4; kk++) {
            const int cur = kk & 1;
            const int nxt = cur ^ 1;
            if (kk < 3)
                load_frags(afr[nxt], bfr[nxt], aA, aB, kk + 1, wm, wn, lrow, lkof);
            mma_block(acc, afr[cur], bfr[cur]);
        }
    }

    // ---- drain pipeline, then reuse smem as fp32 Z tile [128][EPI_PITCH] ----
    asm volatile("cp.async.wait_group 0;" ::: "memory");
    __syncthreads();

    float* zt = reinterpret_cast<float*>(smem);
    {
        const int r0 = wm * 32 + (lane >> 2);
        const int c0 = wn * 64 + (lane & 3) * 2;
#pragma unroll
        for (int mf = 0; mf < 2; mf++) {
            int row = r0 + mf * 16;
#pragma unroll
            for (int n8 = 0; n8 < 8; n8++) {
                int pc = c0 + n8 * 8;
                *reinterpret_cast<float2*>(&zt[(size_t)row * EPI_PITCH + pc]) =
                    make_float2(acc[mf][n8][0], acc[mf][n8][1]);
                *reinterpret_cast<float2*>(&zt[(size_t)(row + 8) * EPI_PITCH + pc]) =
                    make_float2(acc[mf][n8][2], acc[mf][n8][3]);
            }
        }
    }
    __syncthreads();

    // ---- fused LSTM epilogue: warp -> 16-row block, lane -> j ----
    {
        const int j = lane;                  // 0..31
        const int jg = j0 + j;
        const float bfs = bf[jg];
        const float bis = bi[jg];
        const float bos = bo[jg];
        const float bgs = bg[jg];
#pragma unroll
        for (int i = 0; i < 16; i++) {
            int ml = wid * 16 + i;
            float4 z = *reinterpret_cast<const float4*>(&zt[(size_t)ml * EPI_PITCH + j * 4]);
            float zf = z.x + bfs;
            float zi = z.y + bis;
            float zo = z.z + bos;
            float zg = z.w + bgs;
            int m = m0 + ml;
            float co = c_old[(size_t)m * NOUT + jg];
            float f  = sigmoidf_(zf);
            float ii = sigmoidf_(zi);
            float oo = sigmoidf_(zo);
            float g  = tanhf(zg);
            float c  = f * co + ii * g;
            float hh = oo * tanhf(c);
            out[(size_t)m * NOUT + jg] = c;
            out[(size_t)B_ * NOUT + (size_t)m * NOUT + jg] = hh;
        }
    }
}

// ---------------------------------------------------------------------------
// kernel_launch
// Input order: c_old, h_old, x, Wf, bf, Wi, bi, Wo, bo, Wg, bg, mode
// ---------------------------------------------------------------------------
extern "C" void kernel_launch(void* const* d_in, const int* in_sizes, int n_in,
                              void* d_out, int out_size) {
    const float* c_old = (const float*)d_in[0];
    const float* h_old = (const float*)d_in[1];
    const float* x     = (const float*)d_in[2];
    const float* Wf    = (const float*)d_in[3];
    const float* bf    = (const float*)d_in[4];
    const float* Wi    = (const float*)d_in[5];
    const float* bi    = (const float*)d_in[6];
    const float* Wo    = (const float*)d_in[7];
    const float* bo    = (const float*)d_in[8];
    const float* Wg    = (const float*)d_in[9];
    const float* bg    = (const float*)d_in[10];
    float* out = (float*)d_out;

    static int configured = 0;
    if (!configured) {
        cudaFuncSetAttribute(lstm_gemm_fused_kernel,
                             cudaFuncAttributeMaxDynamicSharedMemorySize, SMEM_TOTAL);
        configured = 1;
    }

    conv_all_kernel<<<T_BLOCKS + W_BLOCKS, 256>>>(x, h_old, Wf, Wi, Wo, Wg);

    lstm_gemm_fused_kernel<<<(B_ / BM) * (NTOT / BN), 256, SMEM_TOTAL>>>(
        c_old, bf, bi, bo, bg, out);
}

// round 10
// speedup vs baseline: 1.1408x; 1.0938x over previous
#include <cuda_runtime.h>
#include <cuda_fp16.h>
#include <cstdint>
#include <math.h>

// ---------------------------------------------------------------------------
// Problem constants
// ---------------------------------------------------------------------------
#define B_     4096
#define NIN    2048
#define NOUT   2048
#define KTOT   4096              // NIN + NOUT
#define NTOT   8192              // 4 * NOUT

// GEMM tiling: 128(M) x 128(N-packed) x 64(K), 256 threads, 8 warps (4m x 2n),
// warp tile 32x64, 2 CTAs/SM, strength-reduced addressing.
#define BM     128
#define BN     128
#define BK     64
#define STG    3
#define A_STAGE_B  (BM * BK * 2)             // 16384
#define B_STAGE_B  (BN * BK * 2)             // 16384
#define STAGE_B    (A_STAGE_B + B_STAGE_B)   // 32768
#define SMEM_TOTAL (STG * STAGE_B)           // 98304 -> 2 CTAs/SM
#define EPI_PITCH  132                        // fp32 words per row (128 + 4 pad)

// ---------------------------------------------------------------------------
// Device scratch (static; no allocation allowed)
// ---------------------------------------------------------------------------
__device__ __align__(16) __half g_Th[(size_t)B_ * KTOT];     // 32 MB
__device__ __align__(16) __half g_Wh[(size_t)NTOT * KTOT];   // 64 MB (rows: j*4+gate)

// ---------------------------------------------------------------------------
// Helpers
// ---------------------------------------------------------------------------
__device__ __forceinline__ uint32_t smem_u32(const void* p) {
    uint32_t a;
    asm("{ .reg .u64 t; cvta.to.shared.u64 t, %1; cvt.u32.u64 %0, t; }" : "=r"(a) : "l"(p));
    return a;
}

__device__ __forceinline__ void cp16(uint32_t dst, const void* src) {
    asm volatile("cp.async.cg.shared.global [%0], [%1], 16;" :: "r"(dst), "l"(src));
}

__device__ __forceinline__ void ldsm4(uint32_t* d, uint32_t addr) {
    asm volatile("ldmatrix.sync.aligned.m8n8.x4.shared.b16 {%0,%1,%2,%3}, [%4];"
                 : "=r"(d[0]), "=r"(d[1]), "=r"(d[2]), "=r"(d[3]) : "r"(addr));
}

__device__ __forceinline__ void mma16816(float* c,
                                         uint32_t a0, uint32_t a1, uint32_t a2, uint32_t a3,
                                         uint32_t b0, uint32_t b1) {
    asm volatile("mma.sync.aligned.m16n8k16.row.col.f32.f16.f16.f32 "
                 "{%0,%1,%2,%3}, {%4,%5,%6,%7}, {%8,%9}, {%0,%1,%2,%3};"
                 : "+f"(c[0]), "+f"(c[1]), "+f"(c[2]), "+f"(c[3])
                 : "r"(a0), "r"(a1), "r"(a2), "r"(a3), "r"(b0), "r"(b1));
}

__device__ __forceinline__ float sigmoidf_(float z) { return 1.0f / (1.0f + expf(-z)); }

__device__ __forceinline__ uint32_t packh2(float a, float b) {
    __half2 p = __floats2half2_rn(a, b);
    return *reinterpret_cast<uint32_t*>(&p);
}

// ---------------------------------------------------------------------------
// Fused conversion kernel: fp32 -> fp16 for both T and packed W.
// ---------------------------------------------------------------------------
__device__ __forceinline__ uint4 pack8_h(const float* src) {
    float4 v0 = *reinterpret_cast<const float4*>(src);
    float4 v1 = *reinterpret_cast<const float4*>(src + 4);
    uint4 o;
    o.x = packh2(v0.x, v0.y);
    o.y = packh2(v0.z, v0.w);
    o.z = packh2(v1.x, v1.y);
    o.w = packh2(v1.z, v1.w);
    return o;
}

#define T_BLOCKS ((B_ * 512) / 256)          // 8192
#define W_BLOCKS ((NTOT * 512) / 256)        // 16384

__global__ void __launch_bounds__(256)
conv_all_kernel(const float* __restrict__ x, const float* __restrict__ h,
                const float* __restrict__ Wf, const float* __restrict__ Wi,
                const float* __restrict__ Wo, const float* __restrict__ Wg) {
    uint32_t b = blockIdx.x;
    if (b < T_BLOCKS) {
        uint32_t idx = b * 256 + threadIdx.x;
        uint32_t m = idx >> 9;
        uint32_t k = (idx & 511) * 8;
        const float* src = (k < NIN) ? (x + (size_t)m * NIN + k)
                                     : (h + (size_t)m * NOUT + (k - NIN));
        *reinterpret_cast<uint4*>(g_Th + (size_t)m * KTOT + k) = pack8_h(src);
    } else {
        uint32_t idx = (b - T_BLOCKS) * 256 + threadIdx.x;
        uint32_t jall = idx >> 9;                 // gate*2048 + j
        uint32_t k = (idx & 511) * 8;
        uint32_t gate = jall >> 11;
        uint32_t j = jall & 2047;
        const float* W = (gate == 0) ? Wf : (gate == 1) ? Wi : (gate == 2) ? Wo : Wg;
        uint32_t p = j * 4 + gate;
        *reinterpret_cast<uint4*>(g_Wh + (size_t)p * KTOT + k) =
            pack8_h(W + (size_t)j * KTOT + k);
    }
}

// ---------------------------------------------------------------------------
// Fused GEMM + LSTM epilogue, strength-reduced addressing.
// grid = 2048 (mt = bid&31, nt = bid>>5), 256 threads, 3-stage cp.async.
// ---------------------------------------------------------------------------
__global__ void __launch_bounds__(256, 2)
lstm_gemm_fused_kernel(const float* __restrict__ c_old,
                       const float* __restrict__ bf,
                       const float* __restrict__ bi,
                       const float* __restrict__ bo,
                       const float* __restrict__ bg,
                       float* __restrict__ out) {
    extern __shared__ __align__(1024) char smem[];
    const uint32_t sbase = smem_u32(smem);

    const int t    = threadIdx.x;
    const int lane = t & 31;
    const int wid  = t >> 5;      // 0..7
    const int wm   = wid & 3;     // warp m band: 32 rows
    const int wn   = wid >> 2;    // warp n band: 64 packed cols

    const int bid = blockIdx.x;
    const int mt = bid & 31;
    const int nt = bid >> 5;
    const int m0 = mt * BM;
    const int p0 = nt * BN;       // packed col base
    const int j0 = nt * 32;       // j base

    // ---- cp.async constants (all thread-invariant except the k pointer bump)
    // dst(off) with swizzle: off = row*128 + c16*16, row = t>>3 (+32i), c16 = t&7.
    // swz(off) = off ^ ((row&7)<<4); i*4096 does not touch bits [4:6], so additive.
    const uint32_t xorvt  = (uint32_t)((t >> 3) & 7) << 4;
    const uint32_t dstA0  = (uint32_t)(t >> 3) * 128 + (((uint32_t)(t & 7) * 16) ^ xorvt);
    const uint32_t dstB0  = dstA0 + A_STAGE_B;
    const __half* srcA = g_Th + (size_t)(m0 + (t >> 3)) * KTOT + (t & 7) * 8;
    const __half* srcB = g_Wh + (size_t)(p0 + (t >> 3)) * KTOT + (t & 7) * 8;
    int kptr = 0;   // element offset bumped by BK per fill

    const uint32_t stg0 = sbase;
    const uint32_t stg1 = sbase + STAGE_B;
    const uint32_t stg2 = sbase + 2 * STAGE_B;

    // ---- LDSM constants: addr = stage + rowterm[f] + kx(kk)
    // rowterm = row*128 (row&7 == lane&7 for every fragment);
    // kx = (kk*32 + lkofb) ^ xorv, shared by all 6 fragments.
    const uint32_t lrow  = (uint32_t)(lane & 15);
    const uint32_t lkofb = (lane & 16) ? 16u : 0u;
    const uint32_t xorv  = (uint32_t)(lane & 7) << 4;
    uint32_t rowA[2], rowB[4];
#pragma unroll
    for (int mf = 0; mf < 2; mf++)
        rowA[mf] = (uint32_t)(wm * 32 + mf * 16 + lrow) * 128;
#pragma unroll
    for (int nf = 0; nf < 4; nf++)
        rowB[nf] = A_STAGE_B + (uint32_t)(wn * 64 + nf * 16 + lrow) * 128;

    float acc[2][8][4];           // [mf][n8][quad]
#pragma unroll
    for (int i = 0; i < 2; i++)
#pragma unroll
        for (int j = 0; j < 8; j++)
#pragma unroll
            for (int q = 0; q < 4; q++) acc[i][j][q] = 0.0f;

    // ---- fill one stage: 4 A chunks + 4 B chunks, addresses are base+imm
    auto fill_stage = [&](uint32_t stg) {
        const __half* sa = srcA + kptr;
        const __half* sb = srcB + kptr;
#pragma unroll
        for (int i = 0; i < 4; i++)
            cp16(stg + dstA0 + i * 4096, sa + (size_t)i * 32 * KTOT);
#pragma unroll
        for (int i = 0; i < 4; i++)
            cp16(stg + dstB0 + i * 4096, sb + (size_t)i * 32 * KTOT);
        asm volatile("cp.async.commit_group;" ::: "memory");
        kptr += BK;
    };

    fill_stage(stg0);
    fill_stage(stg1);

    const int NIT = KTOT / BK;     // 64
    uint32_t stg_cur = stg0, stg_nxt = stg1, stg_fill = stg2;

    for (int it = 0; it < NIT; it++) {
        asm volatile("cp.async.wait_group 1;" ::: "memory");
        __syncthreads();

        if (it + 2 < NIT)
            fill_stage(stg_fill);

        const uint32_t aS = stg_cur;

#pragma unroll
        for (int kk = 0; kk < 4; kk++) {
            const uint32_t kx = ((uint32_t)(kk * 32) + lkofb) ^ xorv;
            uint32_t a[2][4], b[4][4];
#pragma unroll
            for (int mf = 0; mf < 2; mf++)
                ldsm4(a[mf], aS + rowA[mf] + kx);
#pragma unroll
            for (int nf = 0; nf < 4; nf++)
                ldsm4(b[nf], aS + rowB[nf] + kx);
#pragma unroll
            for (int nf = 0; nf < 4; nf++) {
#pragma unroll
                for (int mf = 0; mf < 2; mf++) {
                    mma16816(acc[mf][nf * 2],     a[mf][0], a[mf][1], a[mf][2], a[mf][3],
                             b[nf][0], b[nf][2]);
                    mma16816(acc[mf][nf * 2 + 1], a[mf][0], a[mf][1], a[mf][2], a[mf][3],
                             b[nf][1], b[nf][3]);
                }
            }
        }

        // rotate stages
        uint32_t tmp = stg_cur;
        stg_cur = stg_nxt;
        stg_nxt = stg_fill;
        stg_fill = tmp;
    }

    // ---- drain pipeline, then reuse smem as fp32 Z tile [128][EPI_PITCH] ----
    asm volatile("cp.async.wait_group 0;" ::: "memory");
    __syncthreads();

    float* zt = reinterpret_cast<float*>(smem);
    {
        const int r0 = wm * 32 + (lane >> 2);
        const int c0 = wn * 64 + (lane & 3) * 2;
#pragma unroll
        for (int mf = 0; mf < 2; mf++) {
            int row = r0 + mf * 16;
#pragma unroll
            for (int n8 = 0; n8 < 8; n8++) {
                int pc = c0 + n8 * 8;
                *reinterpret_cast<float2*>(&zt[(size_t)row * EPI_PITCH + pc]) =
                    make_float2(acc[mf][n8][0], acc[mf][n8][1]);
                *reinterpret_cast<float2*>(&zt[(size_t)(row + 8) * EPI_PITCH + pc]) =
                    make_float2(acc[mf][n8][2], acc[mf][n8][3]);
            }
        }
    }
    __syncthreads();

    // ---- fused LSTM epilogue: warp -> 16-row block, lane -> j ----
    {
        const int j = lane;                  // 0..31
        const int jg = j0 + j;
        const float bfs = bf[jg];
        const float bis = bi[jg];
        const float bos = bo[jg];
        const float bgs = bg[jg];
#pragma unroll
        for (int i = 0; i < 16; i++) {
            int ml = wid * 16 + i;
            float4 z = *reinterpret_cast<const float4*>(&zt[(size_t)ml * EPI_PITCH + j * 4]);
            float zf = z.x + bfs;
            float zi = z.y + bis;
            float zo = z.z + bos;
            float zg = z.w + bgs;
            int m = m0 + ml;
            float co = c_old[(size_t)m * NOUT + jg];
            float f  = sigmoidf_(zf);
            float ii = sigmoidf_(zi);
            float oo = sigmoidf_(zo);
            float g  = tanhf(zg);
            float c  = f * co + ii * g;
            float hh = oo * tanhf(c);
            out[(size_t)m * NOUT + jg] = c;
            out[(size_t)B_ * NOUT + (size_t)m * NOUT + jg] = hh;
        }
    }
}

// ---------------------------------------------------------------------------
// kernel_launch
// Input order: c_old, h_old, x, Wf, bf, Wi, bi, Wo, bo, Wg, bg, mode
// ---------------------------------------------------------------------------
extern "C" void kernel_launch(void* const* d_in, const int* in_sizes, int n_in,
                              void* d_out, int out_size) {
    const float* c_old = (const float*)d_in[0];
    const float* h_old = (const float*)d_in[1];
    const float* x     = (const float*)d_in[2];
    const float* Wf    = (const float*)d_in[3];
    const float* bf    = (const float*)d_in[4];
    const float* Wi    = (const float*)d_in[5];
    const float* bi    = (const float*)d_in[6];
    const float* Wo    = (const float*)d_in[7];
    const float* bo    = (const float*)d_in[8];
    const float* Wg    = (const float*)d_in[9];
    const float* bg    = (const float*)d_in[10];
    float* out = (float*)d_out;

    static int configured = 0;
    if (!configured) {
        cudaFuncSetAttribute(lstm_gemm_fused_kernel,
                             cudaFuncAttributeMaxDynamicSharedMemorySize, SMEM_TOTAL);
        configured = 1;
    }

    conv_all_kernel<<<T_BLOCKS + W_BLOCKS, 256>>>(x, h_old, Wf, Wi, Wo, Wg);

    lstm_gemm_fused_kernel<<<(B_ / BM) * (NTOT / BN), 256, SMEM_TOTAL>>>(
        c_old, bf, bi, bo, bg, out);
}

// round 12
// speedup vs baseline: 1.1853x; 1.0390x over previous
#include <cuda_runtime.h>
#include <cuda_fp16.h>
#include <cstdint>
#include <math.h>

// ---------------------------------------------------------------------------
// Problem constants
// ---------------------------------------------------------------------------
#define B_     4096
#define NIN    2048
#define NOUT   2048
#define KTOT   4096              // NIN + NOUT
#define NTOT   8192              // 4 * NOUT

// GEMM tiling: 128(M) x 128(N-packed) x 64(K), 256 threads, 8 warps (4m x 2n),
// warp tile 32x64, 2 CTAs/SM, race-free boundary-pipelined fragment loads.
#define BM     128
#define BN     128
#define BK     64
#define STG    3
#define A_STAGE_B  (BM * BK * 2)             // 16384
#define B_STAGE_B  (BN * BK * 2)             // 16384
#define STAGE_B    (A_STAGE_B + B_STAGE_B)   // 32768
#define SMEM_TOTAL (STG * STAGE_B)           // 98304 -> 2 CTAs/SM
#define EPI_PITCH  132                        // fp32 words per row (128 + 4 pad)

// ---------------------------------------------------------------------------
// Device scratch (static; no allocation allowed)
// ---------------------------------------------------------------------------
__device__ __align__(16) __half g_Th[(size_t)B_ * KTOT];     // 32 MB
__device__ __align__(16) __half g_Wh[(size_t)NTOT * KTOT];   // 64 MB (rows: j*4+gate)

// ---------------------------------------------------------------------------
// Helpers
// ---------------------------------------------------------------------------
__device__ __forceinline__ uint32_t smem_u32(const void* p) {
    uint32_t a;
    asm("{ .reg .u64 t; cvta.to.shared.u64 t, %1; cvt.u32.u64 %0, t; }" : "=r"(a) : "l"(p));
    return a;
}

__device__ __forceinline__ void cp16(uint32_t dst, const void* src) {
    asm volatile("cp.async.cg.shared.global [%0], [%1], 16;" :: "r"(dst), "l"(src));
}

__device__ __forceinline__ void ldsm4(uint32_t* d, uint32_t addr) {
    asm volatile("ldmatrix.sync.aligned.m8n8.x4.shared.b16 {%0,%1,%2,%3}, [%4];"
                 : "=r"(d[0]), "=r"(d[1]), "=r"(d[2]), "=r"(d[3]) : "r"(addr));
}

__device__ __forceinline__ void mma16816(float* c,
                                         uint32_t a0, uint32_t a1, uint32_t a2, uint32_t a3,
                                         uint32_t b0, uint32_t b1) {
    asm volatile("mma.sync.aligned.m16n8k16.row.col.f32.f16.f16.f32 "
                 "{%0,%1,%2,%3}, {%4,%5,%6,%7}, {%8,%9}, {%0,%1,%2,%3};"
                 : "+f"(c[0]), "+f"(c[1]), "+f"(c[2]), "+f"(c[3])
                 : "r"(a0), "r"(a1), "r"(a2), "r"(a3), "r"(b0), "r"(b1));
}

__device__ __forceinline__ float sigmoidf_(float z) { return 1.0f / (1.0f + expf(-z)); }

__device__ __forceinline__ uint32_t packh2(float a, float b) {
    __half2 p = __floats2half2_rn(a, b);
    return *reinterpret_cast<uint32_t*>(&p);
}

// ---------------------------------------------------------------------------
// Fused conversion kernel: fp32 -> fp16 for both T and packed W.
// ---------------------------------------------------------------------------
__device__ __forceinline__ uint4 pack8_h(const float* src) {
    float4 v0 = *reinterpret_cast<const float4*>(src);
    float4 v1 = *reinterpret_cast<const float4*>(src + 4);
    uint4 o;
    o.x = packh2(v0.x, v0.y);
    o.y = packh2(v0.z, v0.w);
    o.z = packh2(v1.x, v1.y);
    o.w = packh2(v1.z, v1.w);
    return o;
}

#define T_BLOCKS ((B_ * 512) / 256)          // 8192
#define W_BLOCKS ((NTOT * 512) / 256)        // 16384

__global__ void __launch_bounds__(256)
conv_all_kernel(const float* __restrict__ x, const float* __restrict__ h,
                const float* __restrict__ Wf, const float* __restrict__ Wi,
                const float* __restrict__ Wo, const float* __restrict__ Wg) {
    uint32_t b = blockIdx.x;
    if (b < T_BLOCKS) {
        uint32_t idx = b * 256 + threadIdx.x;
        uint32_t m = idx >> 9;
        uint32_t k = (idx & 511) * 8;
        const float* src = (k < NIN) ? (x + (size_t)m * NIN + k)
                                     : (h + (size_t)m * NOUT + (k - NIN));
        *reinterpret_cast<uint4*>(g_Th + (size_t)m * KTOT + k) = pack8_h(src);
    } else {
        uint32_t idx = (b - T_BLOCKS) * 256 + threadIdx.x;
        uint32_t jall = idx >> 9;                 // gate*2048 + j
        uint32_t k = (idx & 511) * 8;
        uint32_t gate = jall >> 11;
        uint32_t j = jall & 2047;
        const float* W = (gate == 0) ? Wf : (gate == 1) ? Wi : (gate == 2) ? Wo : Wg;
        uint32_t p = j * 4 + gate;
        *reinterpret_cast<uint4*>(g_Wh + (size_t)p * KTOT + k) =
            pack8_h(W + (size_t)j * KTOT + k);
    }
}

// ---------------------------------------------------------------------------
// Fused GEMM + LSTM epilogue. Boundary order: wait_group -> __syncthreads ->
// preload kk0 of next stage; fill(it+2) issues at the top of the next iter,
// overlapping kk0's MMAs. (wait_group is per-thread; reads of other threads'
// cp.async data must stay AFTER the barrier.)
// grid = 2048 (mt = bid&31, nt = bid>>5), 256 threads, 3-stage cp.async.
// ---------------------------------------------------------------------------
__global__ void __launch_bounds__(256, 2)
lstm_gemm_fused_kernel(const float* __restrict__ c_old,
                       const float* __restrict__ bf,
                       const float* __restrict__ bi,
                       const float* __restrict__ bo,
                       const float* __restrict__ bg,
                       float* __restrict__ out) {
    extern __shared__ __align__(1024) char smem[];
    const uint32_t sbase = smem_u32(smem);

    const int t    = threadIdx.x;
    const int lane = t & 31;
    const int wid  = t >> 5;      // 0..7
    const int wm   = wid & 3;     // warp m band: 32 rows
    const int wn   = wid >> 2;    // warp n band: 64 packed cols

    const int bid = blockIdx.x;
    const int mt = bid & 31;
    const int nt = bid >> 5;
    const int m0 = mt * BM;
    const int p0 = nt * BN;       // packed col base
    const int j0 = nt * 32;       // j base

    // ---- cp.async constants
    const uint32_t xorvt  = (uint32_t)((t >> 3) & 7) << 4;
    const uint32_t dstA0  = (uint32_t)(t >> 3) * 128 + (((uint32_t)(t & 7) * 16) ^ xorvt);
    const uint32_t dstB0  = dstA0 + A_STAGE_B;
    const __half* srcA = g_Th + (size_t)(m0 + (t >> 3)) * KTOT + (t & 7) * 8;
    const __half* srcB = g_Wh + (size_t)(p0 + (t >> 3)) * KTOT + (t & 7) * 8;
    int kptr = 0;   // element offset bumped by BK per fill

    const uint32_t stg0 = sbase;
    const uint32_t stg1 = sbase + STAGE_B;
    const uint32_t stg2 = sbase + 2 * STAGE_B;

    // ---- LDSM constants: addr = stage + rowterm[f] + kxv[kk]
    const uint32_t lrow  = (uint32_t)(lane & 15);
    const uint32_t lkofb = (lane & 16) ? 16u : 0u;
    const uint32_t xorv  = (uint32_t)(lane & 7) << 4;
    uint32_t rowA[2], rowB[4], kxv[4];
#pragma unroll
    for (int mf = 0; mf < 2; mf++)
        rowA[mf] = (uint32_t)(wm * 32 + mf * 16 + lrow) * 128;
#pragma unroll
    for (int nf = 0; nf < 4; nf++)
        rowB[nf] = A_STAGE_B + (uint32_t)(wn * 64 + nf * 16 + lrow) * 128;
#pragma unroll
    for (int kk = 0; kk < 4; kk++)
        kxv[kk] = ((uint32_t)(kk * 32) + lkofb) ^ xorv;

    float acc[2][8][4];           // [mf][n8][quad]
#pragma unroll
    for (int i = 0; i < 2; i++)
#pragma unroll
        for (int j = 0; j < 8; j++)
#pragma unroll
            for (int q = 0; q < 4; q++) acc[i][j][q] = 0.0f;

    uint32_t a[2][4], b[4][4];

    auto fill_stage = [&](uint32_t stg) {
        const __half* sa = srcA + kptr;
        const __half* sb = srcB + kptr;
#pragma unroll
        for (int i = 0; i < 4; i++)
            cp16(stg + dstA0 + i * 4096, sa + (size_t)i * 32 * KTOT);
#pragma unroll
        for (int i = 0; i < 4; i++)
            cp16(stg + dstB0 + i * 4096, sb + (size_t)i * 32 * KTOT);
        asm volatile("cp.async.commit_group;" ::: "memory");
        kptr += BK;
    };

    auto load_kk = [&](uint32_t stg, int kk) {
        const uint32_t kx = kxv[kk];
#pragma unroll
        for (int mf = 0; mf < 2; mf++)
            ldsm4(a[mf], stg + rowA[mf] + kx);
#pragma unroll
        for (int nf = 0; nf < 4; nf++)
            ldsm4(b[nf], stg + rowB[nf] + kx);
    };

    auto mma_all = [&]() {
#pragma unroll
        for (int nf = 0; nf < 4; nf++) {
#pragma unroll
            for (int mf = 0; mf < 2; mf++) {
                mma16816(acc[mf][nf * 2],     a[mf][0], a[mf][1], a[mf][2], a[mf][3],
                         b[nf][0], b[nf][2]);
                mma16816(acc[mf][nf * 2 + 1], a[mf][0], a[mf][1], a[mf][2], a[mf][3],
                         b[nf][1], b[nf][3]);
            }
        }
    };

    // ---- prologue: two stages in flight; wait -> BARRIER -> preload kk0
    fill_stage(stg0);
    fill_stage(stg1);
    asm volatile("cp.async.wait_group 1;" ::: "memory");
    __syncthreads();
    load_kk(stg0, 0);

    const int NIT = KTOT / BK;     // 64
    uint32_t stg_cur = stg0, stg_nxt = stg1, stg_fill = stg2;

    for (int it = 0; it < NIT; it++) {
        // fill(it+2): its buffer was released by the barrier at end of it-1;
        // issue overlaps kk0's MMAs.
        if (it + 2 < NIT)
            fill_stage(stg_fill);

        mma_all();                 // kk0 (fragments preloaded before this iter)
#pragma unroll
        for (int kk = 1; kk < 4; kk++) {
            load_kk(stg_cur, kk);
            mma_all();
        }

        // boundary: per-thread wait, BARRIER, then preload next stage's kk0
        if (it + 1 < NIT) {
            if (it + 2 < NIT)
                asm volatile("cp.async.wait_group 1;" ::: "memory");
            else
                asm volatile("cp.async.wait_group 0;" ::: "memory");
            __syncthreads();
            load_kk(stg_nxt, 0);
        }

        uint32_t tmp = stg_cur;
        stg_cur = stg_nxt;
        stg_nxt = stg_fill;
        stg_fill = tmp;
    }

    // ---- drain, then reuse smem as fp32 Z tile [128][EPI_PITCH] ----
    asm volatile("cp.async.wait_group 0;" ::: "memory");
    __syncthreads();

    float* zt = reinterpret_cast<float*>(smem);
    {
        const int r0 = wm * 32 + (lane >> 2);
        const int c0 = wn * 64 + (lane & 3) * 2;
#pragma unroll
        for (int mf = 0; mf < 2; mf++) {
            int row = r0 + mf * 16;
#pragma unroll
            for (int n8 = 0; n8 < 8; n8++) {
                int pc = c0 + n8 * 8;
                *reinterpret_cast<float2*>(&zt[(size_t)row * EPI_PITCH + pc]) =
                    make_float2(acc[mf][n8][0], acc[mf][n8][1]);
                *reinterpret_cast<float2*>(&zt[(size_t)(row + 8) * EPI_PITCH + pc]) =
                    make_float2(acc[mf][n8][2], acc[mf][n8][3]);
            }
        }
    }
    __syncthreads();

    // ---- fused LSTM epilogue: warp -> 16-row block, lane -> j ----
    {
        const int j = lane;                  // 0..31
        const int jg = j0 + j;
        const float bfs = bf[jg];
        const float bis = bi[jg];
        const float bos = bo[jg];
        const float bgs = bg[jg];
#pragma unroll
        for (int i = 0; i < 16; i++) {
            int ml = wid * 16 + i;
            float4 z = *reinterpret_cast<const float4*>(&zt[(size_t)ml * EPI_PITCH + j * 4]);
            float zf = z.x + bfs;
            float zi = z.y + bis;
            float zo = z.z + bos;
            float zg = z.w + bgs;
            int m = m0 + ml;
            float co = c_old[(size_t)m * NOUT + jg];
            float f  = sigmoidf_(zf);
            float ii = sigmoidf_(zi);
            float oo = sigmoidf_(zo);
            float g  = tanhf(zg);
            float c  = f * co + ii * g;
            float hh = oo * tanhf(c);
            out[(size_t)m * NOUT + jg] = c;
            out[(size_t)B_ * NOUT + (size_t)m * NOUT + jg] = hh;
        }
    }
}

// ---------------------------------------------------------------------------
// kernel_launch
// Input order: c_old, h_old, x, Wf, bf, Wi, bi, Wo, bo, Wg, bg, mode
// ---------------------------------------------------------------------------
extern "C" void kernel_launch(void* const* d_in, const int* in_sizes, int n_in,
                              void* d_out, int out_size) {
    const float* c_old = (const float*)d_in[0];
    const float* h_old = (const float*)d_in[1];
    const float* x     = (const float*)d_in[2];
    const float* Wf    = (const float*)d_in[3];
    const float* bf    = (const float*)d_in[4];
    const float* Wi    = (const float*)d_in[5];
    const float* bi    = (const float*)d_in[6];
    const float* Wo    = (const float*)d_in[7];
    const float* bo    = (const float*)d_in[8];
    const float* Wg    = (const float*)d_in[9];
    const float* bg    = (const float*)d_in[10];
    float* out = (float*)d_out;

    static int configured = 0;
    if (!configured) {
        cudaFuncSetAttribute(lstm_gemm_fused_kernel,
                             cudaFuncAttributeMaxDynamicSharedMemorySize, SMEM_TOTAL);
        configured = 1;
    }

    conv_all_kernel<<<T_BLOCKS + W_BLOCKS, 256>>>(x, h_old, Wf, Wi, Wo, Wg);

    lstm_gemm_fused_kernel<<<(B_ / BM) * (NTOT / BN), 256, SMEM_TOTAL>>>(
        c_old, bf, bi, bo, bg, out);
}